// round 14
// baseline (speedup 1.0000x reference)
#include <cuda_runtime.h>
#include <stdint.h>

// Problem constants
#define BB 16
#define CC 4
#define HH 512
#define WW 1024
#define ROWS (BB * CC * HH)       // 32768
#define NBLK (ROWS / 8)           // 4096 blocks, 8 rows each
#define BCN  (BB * CC)            // 64 (b,c) groups; 64 blocks per group

// Per-(b,c) reciprocal weights, padded to 128B lines. Recomputed by kernel A
// every launch — no stale state across graph replays.
__device__ float g_inv[BCN][32];

// ---------------------------------------------------------------------------
// Kernel A (normal launch, 64 blocks x 512 threads): per-group masked-row
// count from vertical_true -> g_inv[bc] = cnt>0 ? 1/(max(cnt,1)*B) : 0.
// Block 0 also zeroes the output scalar (poisoned by the harness).
// ---------------------------------------------------------------------------
__global__ __launch_bounds__(512) void precompute_kernel(
    const float* __restrict__ vertical_true,
    float* __restrict__ out)
{
    const int bc   = blockIdx.x;        // 0..63
    const int t    = threadIdx.x;       // 0..511
    const int lane = t & 31;
    const int wid  = t >> 5;

    float c = (__ldg(&vertical_true[bc * HH + t]) >= 0.5f) ? 1.0f : 0.0f;
#pragma unroll
    for (int off = 16; off > 0; off >>= 1) {
        c += __shfl_xor_sync(0xffffffffu, c, off);
    }

    __shared__ float s_c[16];
    if (lane == 0) s_c[wid] = c;
    __syncthreads();

    if (t == 0) {
        float cnt = 0.0f;
#pragma unroll
        for (int w = 0; w < 16; w++) cnt += s_c[w];
        g_inv[bc][0] = (cnt > 0.0f) ? (1.0f / (fmaxf(cnt, 1.0f) * (float)BB))
                                    : 0.0f;
        if (bc == 0) out[0] = 0.0f;
    }
}

// ---------------------------------------------------------------------------
// Kernel B (normal launch — NOT PDL): exact R7 streaming body. One warp per
// row, 8 rows per block, serial first-max argmax, one __syncthreads. Warp 0
// lane 0 prefetches g_inv[bc] at entry (L2-hot). Tail: reduce 8 row errors,
// thread 0 fires ONE fire-and-forget RED.ADD(out, e*inv). No acquires, no
// recount, no with-return atomics.
// ---------------------------------------------------------------------------
__global__ __launch_bounds__(256) void row_argmax_kernel(
    const float* __restrict__ offset_pred,
    const float* __restrict__ offset_true,
    const float* __restrict__ cls_true,
    const float* __restrict__ vertical_true,
    float* __restrict__ out)
{
    const int warp_in_block = threadIdx.x >> 5;
    const int lane = threadIdx.x & 31;
    const int row = blockIdx.x * 8 + warp_in_block;

    // Prefetch the group reciprocal early so it's ready at the tail.
    float inv = 0.0f;
    if (threadIdx.x == 0) {
        inv = __ldg(&g_inv[blockIdx.x >> 6][0]);
    }

    const float4* crow = reinterpret_cast<const float4*>(cls_true + (size_t)row * WW);

    // Front-batch all 8 coalesced float4 loads (512B/warp each) -> MLP 8.
    float4 v[8];
#pragma unroll
    for (int k = 0; k < 8; k++) {
        v[k] = __ldcs(&crow[k * 32 + lane]);   // streaming: read-once data
    }

    // Per-lane scan in increasing index order (first-max within lane).
    float best = -__int_as_float(0x7f800000);  // -inf
    int   bidx = 0;
#pragma unroll
    for (int k = 0; k < 8; k++) {
        const int base = (k * 32 + lane) * 4;
        if (v[k].x > best) { best = v[k].x; bidx = base + 0; }
        if (v[k].y > best) { best = v[k].y; bidx = base + 1; }
        if (v[k].z > best) { best = v[k].z; bidx = base + 2; }
        if (v[k].w > best) { best = v[k].w; bidx = base + 3; }
    }

    // Warp reduction: larger value wins; exact tie -> smaller index (first-max).
#pragma unroll
    for (int off = 16; off > 0; off >>= 1) {
        float oval = __shfl_xor_sync(0xffffffffu, best, off);
        int   oidx = __shfl_xor_sync(0xffffffffu, bidx, off);
        if (oval > best || (oval == best && oidx < bidx)) {
            best = oval;
            bidx = oidx;
        }
    }

    // Lane 0 of each warp: gather + mask for this row.
    __shared__ float s_err[8];
    if (lane == 0) {
        const size_t gidx = (size_t)row * WW + bidx;
        float p = __ldg(&offset_pred[gidx]);
        float t = __ldg(&offset_true[gidx]);
        float mask = (__ldg(&vertical_true[row]) >= 0.5f) ? 1.0f : 0.0f;
        s_err[warp_in_block] = fabsf(p - t) * mask;
    }
    __syncthreads();

    // Warp 0, lanes 0..7 reduce the 8 row errors; thread 0 fires one RED.
    if (threadIdx.x < 8) {
        float e = s_err[threadIdx.x];
#pragma unroll
        for (int off = 4; off > 0; off >>= 1) {
            e += __shfl_xor_sync(0x000000ffu, e, off);
        }
        if (threadIdx.x == 0) {
            atomicAdd(out, e * inv);           // REDG.ADD (result unused)
        }
    }
}

// ---------------------------------------------------------------------------
extern "C" void kernel_launch(void* const* d_in, const int* in_sizes, int n_in,
                              void* d_out, int out_size)
{
    const float* offset_pred   = (const float*)d_in[0];
    const float* offset_true   = (const float*)d_in[1];
    const float* cls_true      = (const float*)d_in[2];
    const float* vertical_true = (const float*)d_in[3];
    float* out = (float*)d_out;

    // Small node first (serialized), then the clean stream.
    precompute_kernel<<<BCN, 512>>>(vertical_true, out);

    row_argmax_kernel<<<NBLK, 256>>>(offset_pred, offset_true, cls_true,
                                     vertical_true, out);
}